// round 16
// baseline (speedup 1.0000x reference)
#include <cuda_runtime.h>
#include <cuda_fp16.h>

// ---------------------------------------------------------------------------
// GAT 3-layer forward.  N=50000, E=850000 (fixed shapes).
//   CSR: fixed-stride buckets (64 slots/node), memset + one atomic scatter on
//        a side stream; W1/W2 fp16-preconverted there.  W0 converted inside
//        gemm0 (overlaps front-batched x loads).
//   Per layer: HMMA fp16 GEMM (m16n8k16, fp32 accum) + fused el/er + fp16
//              feat store; aggr caches csr/ex in SMEM, x8 gather batches.
//   PIPELINE: aggr_i chunk c -> gemm_{i+1} chunk c (s2), 4 chunks/layer.
//   RACE FIX (R15): gemm_{i+1} writes feat/el/er that aggr_i still gathers
//   from arbitrary rows -> PING-PONG buffers (A for layers 0/2, B for 1).
// ---------------------------------------------------------------------------

#define NNODES 50000
#define SLOTS  64
#define NSLOT  (NNODES * SLOTS)
#define STR 136   // padded smem row stride in halfs
#define NCHUNK 4

__device__ __half g_featA[NNODES * 128];
__device__ __half g_featB[NNODES * 128];
__device__ __half g_hx[NNODES * 128];
__device__ __half g_w1h[128 * 128];
__device__ __half g_w2h[64 * 128];
__device__ float  g_elA[NNODES * 4];
__device__ float  g_erA[NNODES * 4];
__device__ float  g_elB[NNODES * 4];
__device__ float  g_erB[NNODES * 4];
__device__ int    g_deg[NNODES];
__device__ int    g_csr[NSLOT];

// ------------------------------- CSR build --------------------------------

__global__ void k_scatter(const int* __restrict__ src, const int* __restrict__ dst, int E) {
    int base = (blockIdx.x * blockDim.x + threadIdx.x) * 8;
    if (base + 7 < E) {
        int4 s0 = *(const int4*)&src[base];
        int4 s1 = *(const int4*)&src[base + 4];
        int4 d0 = *(const int4*)&dst[base];
        int4 d1 = *(const int4*)&dst[base + 4];
        int p0 = atomicAdd(&g_deg[d0.x], 1);
        int p1 = atomicAdd(&g_deg[d0.y], 1);
        int p2 = atomicAdd(&g_deg[d0.z], 1);
        int p3 = atomicAdd(&g_deg[d0.w], 1);
        int p4 = atomicAdd(&g_deg[d1.x], 1);
        int p5 = atomicAdd(&g_deg[d1.y], 1);
        int p6 = atomicAdd(&g_deg[d1.z], 1);
        int p7 = atomicAdd(&g_deg[d1.w], 1);
        g_csr[d0.x * SLOTS + p0] = s0.x;
        g_csr[d0.y * SLOTS + p1] = s0.y;
        g_csr[d0.z * SLOTS + p2] = s0.z;
        g_csr[d0.w * SLOTS + p3] = s0.w;
        g_csr[d1.x * SLOTS + p4] = s1.x;
        g_csr[d1.y * SLOTS + p5] = s1.y;
        g_csr[d1.z * SLOTS + p6] = s1.z;
        g_csr[d1.w * SLOTS + p7] = s1.w;
    } else {
        for (int k = 0; k < 8; k++)
            if (base + k < E) {
                int d = dst[base + k];
                int p = atomicAdd(&g_deg[d], 1);
                g_csr[d * SLOTS + p] = src[base + k];
            }
    }
}

__global__ void k_wcvt(const float* __restrict__ W, __half* __restrict__ Wh, int nel) {
    int i = (blockIdx.x * blockDim.x + threadIdx.x) * 4;
    if (i < nel) {
        float4 v = *(const float4*)&W[i];
        __half2 h0 = __floats2half2_rn(v.x, v.y);
        __half2 h1 = __floats2half2_rn(v.z, v.w);
        *(__half2*)&Wh[i] = h0;
        *(__half2*)&Wh[i + 2] = h1;
    }
}

// ----------------------- HMMA GEMM + el/er + fp16 store --------------------

__device__ __forceinline__ unsigned smaddr(const void* p) {
    return (unsigned)__cvta_generic_to_shared(p);
}

__device__ __forceinline__ void ldsm_x4(unsigned& r0, unsigned& r1, unsigned& r2,
                                        unsigned& r3, unsigned a) {
    asm volatile("ldmatrix.sync.aligned.m8n8.x4.shared.b16 {%0,%1,%2,%3}, [%4];"
                 : "=r"(r0), "=r"(r1), "=r"(r2), "=r"(r3) : "r"(a));
}

__device__ __forceinline__ void hmma16816(float* c, unsigned a0, unsigned a1,
                                          unsigned a2, unsigned a3,
                                          unsigned b0, unsigned b1) {
    asm volatile("mma.sync.aligned.m16n8k16.row.col.f32.f16.f16.f32 "
                 "{%0,%1,%2,%3}, {%4,%5,%6,%7}, {%8,%9}, {%0,%1,%2,%3};"
                 : "+f"(c[0]), "+f"(c[1]), "+f"(c[2]), "+f"(c[3])
                 : "r"(a0), "r"(a1), "r"(a2), "r"(a3), "r"(b0), "r"(b1));
}

// XH: x dtype (0 fp32 batched convert, 1 fp16 raw).
// WH: W dtype (0 fp32 in-kernel convert, 1 fp16 raw).  Rows [roff, nend).
// el_o/er_o: attention-dot output buffers (ping-pong).
template <int OUT, int H, int XH, int WH>
__global__ void __launch_bounds__(256, 4) k_gemmh(const void* __restrict__ xv,
                                                  const void* __restrict__ Wv,
                                                  const float* __restrict__ al,
                                                  const float* __restrict__ ar,
                                                  __half* __restrict__ feat,
                                                  float* __restrict__ el_o,
                                                  float* __restrict__ er_o,
                                                  int roff, int nend) {
    constexpr int NT = OUT / 16;
    extern __shared__ __half shh[];
    __half* w_sh = shh;                        // [OUT][STR]
    __half* x_sh = shh + OUT * STR;            // [64][STR]
    float*  red  = (float*)(x_sh + 64 * STR);  // H==1 cross-warp combine

    int tid = threadIdx.x;
    int r0 = roff + blockIdx.x * 64;

    if constexpr (WH == 0) {
        const float* W = (const float*)Wv;
        for (int idx = tid; idx < OUT * 32; idx += 256) {
            int c = idx >> 5;
            int k4 = idx & 31;
            float4 wv = *(const float4*)&W[c * 128 + k4 * 4];
            __half2 h0 = __floats2half2_rn(wv.x, wv.y);
            __half2 h1 = __floats2half2_rn(wv.z, wv.w);
            uint2 pk = make_uint2(*(unsigned*)&h0, *(unsigned*)&h1);
            *(uint2*)&w_sh[c * STR + k4 * 4] = pk;
        }
    } else {
        const uint4* Wp = (const uint4*)Wv;    // 16B = 8 halfs
        for (int idx = tid; idx < OUT * 16; idx += 256) {
            int c = idx >> 4;
            int q = idx & 15;
            uint4 v = Wp[c * 16 + q];
            *(uint4*)&w_sh[c * STR + q * 8] = v;
        }
    }
    if constexpr (XH == 0) {
        // Front-batched: all 8 LDG.128 issued before any convert/STS (MLP 8).
        const float* x = (const float*)xv;
        float4 v[8];
#pragma unroll
        for (int q = 0; q < 8; q++) {
            int idx = tid + q * 256;
            int r = idx >> 5;
            int k4 = idx & 31;
            int row = r0 + r;
            v[q] = make_float4(0.f, 0.f, 0.f, 0.f);
            if (row < nend) v[q] = *(const float4*)&x[(size_t)row * 128 + k4 * 4];
        }
#pragma unroll
        for (int q = 0; q < 8; q++) {
            int idx = tid + q * 256;
            int r = idx >> 5;
            int k4 = idx & 31;
            __half2 h0 = __floats2half2_rn(v[q].x, v[q].y);
            __half2 h1 = __floats2half2_rn(v[q].z, v[q].w);
            uint2 pk = make_uint2(*(unsigned*)&h0, *(unsigned*)&h1);
            *(uint2*)&x_sh[r * STR + k4 * 4] = pk;
        }
    } else {
        const uint4* xh = (const uint4*)xv;
        for (int idx = tid; idx < 64 * 16; idx += 256) {
            int r = idx >> 4;
            int q = idx & 15;
            int row = r0 + r;
            uint4 v = make_uint4(0u, 0u, 0u, 0u);
            if (row < nend) v = xh[(size_t)row * 16 + q];
            *(uint4*)&x_sh[r * STR + q * 8] = v;
        }
    }
    __syncthreads();

    int wid = tid >> 5, lane = tid & 31;
    int rt = wid >> 1;
    int ch = wid & 1;
    int c0 = ch * (OUT / 2);
    int g = lane >> 2, tig = lane & 3;

    float acc[NT][4];
#pragma unroll
    for (int j = 0; j < NT; j++) { acc[j][0] = acc[j][1] = acc[j][2] = acc[j][3] = 0.f; }

    unsigned a_base = smaddr(&x_sh[(rt * 16 + (lane & 15)) * STR + ((lane >> 4) << 3)]);

#pragma unroll
    for (int k = 0; k < 128; k += 16) {
        unsigned a0, a1, a2, a3;
        ldsm_x4(a0, a1, a2, a3, a_base + k * 2);
#pragma unroll
        for (int jp = 0; jp < NT / 2; jp++) {
            int j = jp * 2;
            int bl = lane & 7;
            int sel = lane >> 3;
            int brow = c0 + 8 * (j + (sel >> 1)) + bl;
            int bk = k + ((sel & 1) << 3);
            unsigned b0, b1, b2, b3;
            ldsm_x4(b0, b1, b2, b3, smaddr(&w_sh[brow * STR + bk]));
            hmma16816(acc[j],     a0, a1, a2, a3, b0, b1);
            hmma16816(acc[j + 1], a0, a1, a2, a3, b2, b3);
        }
    }

    int row_a = r0 + rt * 16 + g;
    int row_b = row_a + 8;

    if constexpr (H == 4) {
        float elp[2][2] = {{0.f, 0.f}, {0.f, 0.f}};
        float erp[2][2] = {{0.f, 0.f}, {0.f, 0.f}};
#pragma unroll
        for (int j = 0; j < NT; j++) {
            int c = c0 + 8 * j + 2 * tig;
            float2 alc = *(const float2*)&al[c];
            float2 arc = *(const float2*)&ar[c];
            int hh = j >> 2;
            elp[hh][0] += acc[j][0] * alc.x + acc[j][1] * alc.y;
            elp[hh][1] += acc[j][2] * alc.x + acc[j][3] * alc.y;
            erp[hh][0] += acc[j][0] * arc.x + acc[j][1] * arc.y;
            erp[hh][1] += acc[j][2] * arc.x + acc[j][3] * arc.y;
            if (row_a < nend) {
                __half2 h = __floats2half2_rn(acc[j][0], acc[j][1]);
                *(__half2*)&feat[(size_t)row_a * OUT + c] = h;
            }
            if (row_b < nend) {
                __half2 h = __floats2half2_rn(acc[j][2], acc[j][3]);
                *(__half2*)&feat[(size_t)row_b * OUT + c] = h;
            }
        }
#pragma unroll
        for (int hh = 0; hh < 2; hh++)
#pragma unroll
            for (int rr = 0; rr < 2; rr++) {
#pragma unroll
                for (int s = 1; s <= 2; s <<= 1) {
                    elp[hh][rr] += __shfl_xor_sync(0xffffffffu, elp[hh][rr], s);
                    erp[hh][rr] += __shfl_xor_sync(0xffffffffu, erp[hh][rr], s);
                }
            }
        if (tig == 0) {
            int hb = ch * 2;
            if (row_a < nend) {
                el_o[row_a * 4 + hb + 0] = elp[0][0];
                el_o[row_a * 4 + hb + 1] = elp[1][0];
                er_o[row_a * 4 + hb + 0] = erp[0][0];
                er_o[row_a * 4 + hb + 1] = erp[1][0];
            }
            if (row_b < nend) {
                el_o[row_b * 4 + hb + 0] = elp[0][1];
                el_o[row_b * 4 + hb + 1] = elp[1][1];
                er_o[row_b * 4 + hb + 0] = erp[0][1];
                er_o[row_b * 4 + hb + 1] = erp[1][1];
            }
        }
    } else {
        float elp[2] = {0.f, 0.f}, erp[2] = {0.f, 0.f};
#pragma unroll
        for (int j = 0; j < NT; j++) {
            int c = c0 + 8 * j + 2 * tig;
            float2 alc = *(const float2*)&al[c];
            float2 arc = *(const float2*)&ar[c];
            elp[0] += acc[j][0] * alc.x + acc[j][1] * alc.y;
            elp[1] += acc[j][2] * alc.x + acc[j][3] * alc.y;
            erp[0] += acc[j][0] * arc.x + acc[j][1] * arc.y;
            erp[1] += acc[j][2] * arc.x + acc[j][3] * arc.y;
            if (row_a < nend) {
                __half2 h = __floats2half2_rn(acc[j][0], acc[j][1]);
                *(__half2*)&feat[(size_t)row_a * OUT + c] = h;
            }
            if (row_b < nend) {
                __half2 h = __floats2half2_rn(acc[j][2], acc[j][3]);
                *(__half2*)&feat[(size_t)row_b * OUT + c] = h;
            }
        }
#pragma unroll
        for (int rr = 0; rr < 2; rr++) {
#pragma unroll
            for (int s = 1; s <= 2; s <<= 1) {
                elp[rr] += __shfl_xor_sync(0xffffffffu, elp[rr], s);
                erp[rr] += __shfl_xor_sync(0xffffffffu, erp[rr], s);
            }
        }
        if (tig == 0) {
            int lr_a = rt * 16 + g, lr_b = lr_a + 8;
            red[lr_a * 2 + ch] = elp[0];
            red[lr_b * 2 + ch] = elp[1];
            red[128 + lr_a * 2 + ch] = erp[0];
            red[128 + lr_b * 2 + ch] = erp[1];
        }
        __syncthreads();
        if (tid < 64) {
            int row = r0 + tid;
            if (row < nend) {
                el_o[row] = red[tid * 2] + red[tid * 2 + 1];
                er_o[row] = red[128 + tid * 2] + red[128 + tid * 2 + 1];
            }
        }
    }
}

// ------------------ edge softmax + message aggregation --------------------

template <int H, int DH, int RELU, int OH>
__global__ void k_aggr(const __half* __restrict__ feat,
                       const float* __restrict__ el,
                       const float* __restrict__ er,
                       const float* __restrict__ bias,
                       void* __restrict__ outv, int roff, int nend) {
    constexpr int HD = H * DH;
    constexpr int FPL = HD / 32;
    __shared__ int   s_csr[8][SLOTS];
    __shared__ float s_ex[8][SLOTS * H];

    int t = blockIdx.x * blockDim.x + threadIdx.x;
    int w = roff + (t >> 5);
    int lane = t & 31;
    if (w >= nend) return;
    int ws = (threadIdx.x >> 5);

    int beg = w * SLOTS;
    int deg = g_deg[w];

    float ern[H];
#pragma unroll
    for (int h = 0; h < H; h++) ern[h] = er[w * H + h];

    float den[H];
#pragma unroll
    for (int h = 0; h < H; h++) den[h] = 0.f;

    for (int i = lane; i < deg; i += 32) {
        int s = g_csr[beg + i];
        s_csr[ws][i] = s;
        if constexpr (H == 4) {
            float4 elv = *(const float4*)&el[s * 4];
            float e0 = elv.x + ern[0]; e0 = e0 > 0.f ? e0 : 0.2f * e0;
            float e1 = elv.y + ern[1]; e1 = e1 > 0.f ? e1 : 0.2f * e1;
            float e2 = elv.z + ern[2]; e2 = e2 > 0.f ? e2 : 0.2f * e2;
            float e3 = elv.w + ern[3]; e3 = e3 > 0.f ? e3 : 0.2f * e3;
            float x0 = __expf(e0), x1 = __expf(e1), x2 = __expf(e2), x3 = __expf(e3);
            *(float4*)&s_ex[ws][i * 4] = make_float4(x0, x1, x2, x3);
            den[0] += x0; den[1] += x1; den[2] += x2; den[3] += x3;
        } else {
            float e = el[s] + ern[0];
            e = e > 0.f ? e : 0.2f * e;
            float x = __expf(e);
            s_ex[ws][i] = x;
            den[0] += x;
        }
    }
#pragma unroll
    for (int h = 0; h < H; h++) {
#pragma unroll
        for (int s = 16; s > 0; s >>= 1) den[h] += __shfl_xor_sync(0xffffffffu, den[h], s);
    }
    float inv0 = 1.0f / den[0];
    float myinv;
    int myh = (lane * FPL) / DH;
    if constexpr (H == 4) {
        float inv1 = 1.0f / den[1], inv2 = 1.0f / den[2], inv3 = 1.0f / den[3];
        myinv = myh == 0 ? inv0 : (myh == 1 ? inv1 : (myh == 2 ? inv2 : inv3));
    } else {
        myinv = inv0;
    }
    __syncwarp();

    float acc[FPL];
#pragma unroll
    for (int j = 0; j < FPL; j++) acc[j] = 0.f;

    int i = 0;
    for (; i + 8 <= deg; i += 8) {
        int sC[8];
        float eC[8];
#pragma unroll
        for (int q = 0; q < 8; q++) {
            sC[q] = s_csr[ws][i + q];
            if constexpr (H == 4) eC[q] = s_ex[ws][(i + q) * 4 + myh];
            else                  eC[q] = s_ex[ws][i + q];
        }
        if constexpr (H == 4) {
            uint2 uu[8];
#pragma unroll
            for (int q = 0; q < 8; q++)
                uu[q] = *(const uint2*)&feat[(size_t)sC[q] * HD + lane * 4];
#pragma unroll
            for (int q = 0; q < 8; q++) {
                float a = eC[q] * myinv;
                float2 f0 = __half22float2(*(__half2*)&uu[q].x);
                float2 f1 = __half22float2(*(__half2*)&uu[q].y);
                acc[0] += a * f0.x; acc[1] += a * f0.y;
                acc[2] += a * f1.x; acc[3] += a * f1.y;
            }
        } else {
            unsigned uu[8];
#pragma unroll
            for (int q = 0; q < 8; q++)
                uu[q] = *(const unsigned*)&feat[(size_t)sC[q] * HD + lane * 2];
#pragma unroll
            for (int q = 0; q < 8; q++) {
                float a = eC[q] * myinv;
                float2 f = __half22float2(*(__half2*)&uu[q]);
                acc[0] += a * f.x; acc[1] += a * f.y;
            }
        }
    }
    for (; i < deg; i++) {
        int s = s_csr[ws][i];
        if constexpr (H == 4) {
            float a = s_ex[ws][i * 4 + myh] * myinv;
            uint2 u = *(const uint2*)&feat[(size_t)s * HD + lane * 4];
            float2 f0 = __half22float2(*(__half2*)&u.x);
            float2 f1 = __half22float2(*(__half2*)&u.y);
            acc[0] += a * f0.x; acc[1] += a * f0.y;
            acc[2] += a * f1.x; acc[3] += a * f1.y;
        } else {
            float a = s_ex[ws][i] * myinv;
            unsigned u = *(const unsigned*)&feat[(size_t)s * HD + lane * 2];
            float2 f0 = __half22float2(*(__half2*)&u);
            acc[0] += a * f0.x; acc[1] += a * f0.y;
        }
    }

    if constexpr (FPL == 4) {
        float4 b = *(const float4*)&bias[lane * 4];
        float4 o = make_float4(acc[0] + b.x, acc[1] + b.y, acc[2] + b.z, acc[3] + b.w);
        if (RELU) {
            o.x = fmaxf(o.x, 0.f); o.y = fmaxf(o.y, 0.f);
            o.z = fmaxf(o.z, 0.f); o.w = fmaxf(o.w, 0.f);
        }
        if constexpr (OH) {
            __half* out = (__half*)outv;
            __half2 h0 = __floats2half2_rn(o.x, o.y);
            __half2 h1 = __floats2half2_rn(o.z, o.w);
            uint2 pk = make_uint2(*(unsigned*)&h0, *(unsigned*)&h1);
            *(uint2*)&out[(size_t)w * HD + lane * 4] = pk;
        } else {
            float* out = (float*)outv;
            *(float4*)&out[(size_t)w * HD + lane * 4] = o;
        }
    } else {
        float2 b = *(const float2*)&bias[lane * 2];
        float2 o = make_float2(acc[0] + b.x, acc[1] + b.y);
        if (RELU) { o.x = fmaxf(o.x, 0.f); o.y = fmaxf(o.y, 0.f); }
        if constexpr (OH) {
            __half* out = (__half*)outv;
            __half2 h = __floats2half2_rn(o.x, o.y);
            *(__half2*)&out[(size_t)w * HD + lane * 2] = h;
        } else {
            float* out = (float*)outv;
            *(float2*)&out[(size_t)w * HD + lane * 2] = o;
        }
    }
}

// ------------------------------- launch -----------------------------------

extern "C" void kernel_launch(void* const* d_in, const int* in_sizes, int n_in,
                              void* d_out, int out_size) {
    const float* feats = (const float*)d_in[0];
    const int*   src   = (const int*)d_in[1];
    const int*   dst   = (const int*)d_in[2];
    const float* W0 = (const float*)d_in[3];
    const float* al0 = (const float*)d_in[4];
    const float* ar0 = (const float*)d_in[5];
    const float* b0 = (const float*)d_in[6];
    const float* W1 = (const float*)d_in[7];
    const float* al1 = (const float*)d_in[8];
    const float* ar1 = (const float*)d_in[9];
    const float* b1 = (const float*)d_in[10];
    const float* W2 = (const float*)d_in[11];
    const float* al2 = (const float*)d_in[12];
    const float* ar2 = (const float*)d_in[13];
    const float* b2 = (const float*)d_in[14];
    float* out = (float*)d_out;

    int n = in_sizes[0] / 128;   // 50000
    int E = in_sizes[1];         // 850000

    const int smem128 = (128 * STR + 64 * STR) * 2 + 1024;  // 53248 B
    const int smem64  = (64 * STR + 64 * STR) * 2 + 1024;   // 35840 B
    cudaFuncSetAttribute(k_gemmh<128, 4, 0, 0>, cudaFuncAttributeMaxDynamicSharedMemorySize, smem128);
    cudaFuncSetAttribute(k_gemmh<128, 4, 1, 1>, cudaFuncAttributeMaxDynamicSharedMemorySize, smem128);
    cudaFuncSetAttribute(k_gemmh<64, 1, 1, 1>,  cudaFuncAttributeMaxDynamicSharedMemorySize, smem64);

    __half *fA = nullptr, *fB = nullptr, *hx = nullptr, *w1h = nullptr, *w2h = nullptr;
    float *elA = nullptr, *erA = nullptr, *elB = nullptr, *erB = nullptr;
    int* degp = nullptr;
    cudaGetSymbolAddress((void**)&fA, g_featA);
    cudaGetSymbolAddress((void**)&fB, g_featB);
    cudaGetSymbolAddress((void**)&hx, g_hx);
    cudaGetSymbolAddress((void**)&w1h, g_w1h);
    cudaGetSymbolAddress((void**)&w2h, g_w2h);
    cudaGetSymbolAddress((void**)&elA, g_elA);
    cudaGetSymbolAddress((void**)&erA, g_erA);
    cudaGetSymbolAddress((void**)&elB, g_elB);
    cudaGetSymbolAddress((void**)&erB, g_erB);
    cudaGetSymbolAddress((void**)&degp, g_deg);

    static cudaStream_t s2 = nullptr;
    static cudaEvent_t ev_fork = nullptr, ev_prep = nullptr;
    static cudaEvent_t ev_a0[NCHUNK], ev_a1[NCHUNK], ev_g1 = nullptr, ev_g2 = nullptr;
    if (!s2) {
        cudaStreamCreateWithFlags(&s2, cudaStreamNonBlocking);
        cudaEventCreateWithFlags(&ev_fork, cudaEventDisableTiming);
        cudaEventCreateWithFlags(&ev_prep, cudaEventDisableTiming);
        cudaEventCreateWithFlags(&ev_g1, cudaEventDisableTiming);
        cudaEventCreateWithFlags(&ev_g2, cudaEventDisableTiming);
        for (int c = 0; c < NCHUNK; c++) {
            cudaEventCreateWithFlags(&ev_a0[c], cudaEventDisableTiming);
            cudaEventCreateWithFlags(&ev_a1[c], cudaEventDisableTiming);
        }
    }

    int e8b = (E + 2047) / 2048;
    int gb_all = (n + 63) / 64;

    // Chunk boundaries, gemm-tile (64) aligned.
    int bnd[NCHUNK + 1];
    for (int c = 0; c <= NCHUNK; c++) {
        int b = (int)(((long long)n * c / NCHUNK + 63) / 64) * 64;
        bnd[c] = b > n ? n : b;
    }
    bnd[NCHUNK] = n;

    // Fork: side stream: CSR build + W1/W2 converts.
    cudaEventRecord(ev_fork, 0);
    cudaStreamWaitEvent(s2, ev_fork, 0);
    cudaMemsetAsync(degp, 0, n * sizeof(int), s2);
    k_scatter<<<e8b, 256, 0, s2>>>(src, dst, E);
    k_wcvt<<<16, 256, 0, s2>>>(W1, w1h, 128 * 128);
    k_wcvt<<<8, 256, 0, s2>>>(W2, w2h, 64 * 128);
    cudaEventRecord(ev_prep, s2);

    // Layer 0 GEMM -> buffers A (fp32 x + fp32 W, both converted in-kernel).
    k_gemmh<128, 4, 0, 0><<<gb_all, 256, smem128>>>(feats, W0, al0, ar0,
                                                    fA, elA, erA, 0, n);

    cudaStreamWaitEvent(0, ev_prep, 0);

    // Layer 0 aggr (reads A) chunks -> layer 1 gemm (writes B) chunks on s2.
    for (int c = 0; c < NCHUNK; c++) {
        int lo = bnd[c], hi = bnd[c + 1];
        k_aggr<4, 32, 1, 1><<<(hi - lo + 7) / 8, 256>>>(fA, elA, erA, b0, hx, lo, hi);
        cudaEventRecord(ev_a0[c], 0);
        cudaStreamWaitEvent(s2, ev_a0[c], 0);
        k_gemmh<128, 4, 1, 1><<<(hi - lo + 63) / 64, 256, smem128, s2>>>(
            hx, w1h, al1, ar1, fB, elB, erB, lo, hi);
    }
    cudaEventRecord(ev_g1, s2);
    cudaStreamWaitEvent(0, ev_g1, 0);

    // Layer 1 aggr (reads B) chunks -> layer 2 gemm (writes A) chunks on s2.
    // (A's previous consumer, aggr0, fully precedes gemm2 via the dep chain.)
    for (int c = 0; c < NCHUNK; c++) {
        int lo = bnd[c], hi = bnd[c + 1];
        k_aggr<4, 32, 1, 1><<<(hi - lo + 7) / 8, 256>>>(fB, elB, erB, b1, hx, lo, hi);
        cudaEventRecord(ev_a1[c], 0);
        cudaStreamWaitEvent(s2, ev_a1[c], 0);
        k_gemmh<64, 1, 1, 1><<<(hi - lo + 63) / 64, 256, smem64, s2>>>(
            hx, w2h, al2, ar2, fA, elA, erA, lo, hi);
    }
    cudaEventRecord(ev_g2, s2);
    cudaStreamWaitEvent(0, ev_g2, 0);

    // Final aggregation (reads A, fp32 to d_out).
    k_aggr<1, 64, 0, 0><<<(n + 7) / 8, 256>>>(fA, elA, erA, b2, out, 0, n);
}